// round 14
// baseline (speedup 1.0000x reference)
#include <cuda_runtime.h>
#include <cstdint>

// ---------------- problem dims ----------------
#define Bsz   64
#define Tsz   512
#define Dsz   128
#define Hsz   512
#define HB    (Hsz * Bsz)        // 32768 floats per h buffer
#define NCTA  128
#define TPB   512
#define L0CTAS 64
#define KC    128                // k-chunk staged per inner pass
#define STRD  132                // stage row stride in floats (pad 4 -> conflict-free LDS.128)
#define STG   (Bsz * STRD)       // 8448 floats per stage buffer

#define WH_FLOATS (24 * Hsz)     // 12288 (24 gate-rows x 512 k)
#define WX_FLOATS (24 * Hsz)     // same stride for both layers (L0 uses k<128)
#define SMEM_FLOATS (WH_FLOATS + WX_FLOATS + 2 * STG)
#define SMEM_BYTES  (SMEM_FLOATS * 4)                 // 165888 B

typedef unsigned long long ull;

// ---------------- persistent device state ----------------
__device__ __align__(16) float g_xT[Tsz * Bsz * Dsz];   // X transposed to [t][b][d]
__device__ __align__(16) float g_h1[2 * HB];            // layer0 hidden, double buffered, [b][k]
__device__ __align__(16) float g_h2[2 * HB];            // layer1 hidden, double buffered, [b][k]
__device__ unsigned g_flags[NCTA];                      // zero-init; reset at kernel end
__device__ unsigned g_release;                          // zero-init; reset at kernel end

// packed f32x2 FMA: full fp32 rate (plain 3-reg FFMA is half rate on sm_103a)
#define FMA2(acc, w, x) asm("fma.rn.f32x2 %0, %1, %2, %0;" : "+l"(acc) : "l"(w), "l"(x))

__device__ __forceinline__ float sum2(ull v) {
    float lo, hi;
    asm("mov.b64 {%0, %1}, %2;" : "=f"(lo), "=f"(hi) : "l"(v));
    return lo + hi;
}
__device__ __forceinline__ float sigmoidf_(float x) {
    return __fdividef(1.0f, 1.0f + __expf(-x));
}
__device__ __forceinline__ float tanhf_(float x) {
    x = fminf(12.0f, fmaxf(-12.0f, x));
    float e = __expf(2.0f * x);
    return __fdividef(e - 1.0f, e + 1.0f);
}
__device__ __forceinline__ uint32_t smem_to_u32(const void* smem_ptr) {
    uint32_t addr;
    asm("{ .reg .u64 tmp; cvta.to.shared.u64 tmp, %1; cvt.u32.u64 %0, tmp; }"
        : "=r"(addr) : "l"(smem_ptr));
    return addr;
}

// cp.async: 16B global->shared via L2 (L2 is the cross-CTA coherence point)
__device__ __forceinline__ void cpasync16(uint32_t smem_dst, const float* gsrc) {
    asm volatile("cp.async.cg.shared.global [%0], [%1], 16;" :: "r"(smem_dst), "l"(gsrc));
}
__device__ __forceinline__ void cpasync_commit() { asm volatile("cp.async.commit_group;"); }
__device__ __forceinline__ void cpasync_wait0()  { asm volatile("cp.async.wait_group 0;"); }

// ---------------- grid barrier: distributed flags + CTA0 aggregation ----------------
__device__ __forceinline__ void gridbar(unsigned val, int cta, int tid) {
    __syncthreads();
    if (tid == 0) {
        __threadfence();
        *((volatile unsigned*)&g_flags[cta]) = val;
    }
    if (cta == 0) {
        if (tid < NCTA) {
            volatile unsigned* f = &g_flags[tid];
            while (*f < val) __nanosleep(32);
        }
        __syncthreads();
        if (tid == 0) {
            __threadfence();
            *((volatile unsigned*)&g_release) = val;
        }
    }
    if (tid == 0) {
        volatile unsigned* r = &g_release;
        while (*r < val) __nanosleep(32);
        __threadfence();
    }
    __syncthreads();
}

// prefetch one 64 x KC chunk into stage ([b][k], stride STRD): 4 x 16B per thread
__device__ __forceinline__ void prefetch_chunk(uint32_t dst, const float* __restrict__ src,
                                               int rstride, int tid) {
#pragma unroll
    for (int i = 0; i < (Bsz * KC) / (4 * TPB); ++i) {     // 4 iters
        int j = tid + i * TPB;
        int b = j >> 5, kq = j & 31;                       // 32 x 16B = one 128-float row
        cpasync16(dst + b * (STRD * 4) + kq * 16, src + (size_t)b * rstride + kq * 4);
    }
    cpasync_commit();
}

// accumulate one KC chunk: thread owns 3 gate-rows (1 unit) x 1 batch col.
// acc[g] packs (even-k, odd-k) partial sums; summed at the end.
__device__ __forceinline__ void accum_chunk(const float* __restrict__ w0,
                                            const float* __restrict__ w1,
                                            const float* __restrict__ w2,
                                            const float* __restrict__ hrow,
                                            ull acc[3]) {
#pragma unroll 8
    for (int kk = 0; kk < KC; kk += 4) {
        ulonglong2 h01 = *reinterpret_cast<const ulonglong2*>(hrow + kk);  // 4 k (LDS.128)
        ulonglong2 wr  = *reinterpret_cast<const ulonglong2*>(w0 + kk);    // broadcast
        ulonglong2 wz  = *reinterpret_cast<const ulonglong2*>(w1 + kk);
        ulonglong2 wn  = *reinterpret_cast<const ulonglong2*>(w2 + kk);
        FMA2(acc[0], wr.x, h01.x); FMA2(acc[0], wr.y, h01.y);
        FMA2(acc[1], wz.x, h01.x); FMA2(acc[1], wz.y, h01.y);
        FMA2(acc[2], wn.x, h01.x); FMA2(acc[2], wn.y, h01.y);
    }
}

__global__ __launch_bounds__(TPB)
void gru_persistent(const float* __restrict__ X,
                    const float* __restrict__ W_ih0, const float* __restrict__ W_hh0,
                    const float* __restrict__ b_ih0, const float* __restrict__ b_hh0,
                    const float* __restrict__ W_ih1, const float* __restrict__ W_hh1,
                    const float* __restrict__ b_ih1, const float* __restrict__ b_hh1,
                    const float* __restrict__ W_fc,  const float* __restrict__ b_fc,
                    float* __restrict__ out) {
    extern __shared__ float smem[];
    float* WHs   = smem;                       // [24 gate-rows][512 k]
    float* WXs   = smem + WH_FLOATS;           // [24 gate-rows][512 k] (L0 uses k<128)
    float* stage = smem + WH_FLOATS + WX_FLOATS;  // [2][64 b][STRD]
    const uint32_t stage_smem = smem_to_u32(stage);

    const int tid  = threadIdx.x;
    const int cta  = blockIdx.x;
    const int col  = tid & 63;                 // batch col this thread owns
    const int unit = tid >> 6;                 // 0..7: local hidden unit

    const bool role0 = (cta < L0CTAS);
    const int  lcta  = role0 ? cta : (cta - L0CTAS);
    const int  U0    = lcta * 8;
    const int  Kx    = role0 ? Dsz : Hsz;
    const int  NCH   = 4 + Kx / KC;            // 4 H chunks + Kx/KC X chunks

    const float* Whh = role0 ? W_hh0 : W_hh1;
    const float* Wih = role0 ? W_ih0 : W_ih1;
    const float* bih = role0 ? b_ih0 : b_ih1;
    const float* bhh = role0 ? b_hh0 : b_hh1;
    float* hbuf = role0 ? g_h1 : g_h2;

    // ---- prologue: zero h buffers ----
    {
        int gid = cta * TPB + tid;
        for (int i = gid; i < 2 * HB; i += NCTA * TPB) {
            __stcg(&g_h1[i], 0.0f);
            __stcg(&g_h2[i], 0.0f);
        }
    }
    // ---- prologue: transpose X[b][t][d] -> g_xT[t][b][d] ; 4 timesteps per CTA ----
    for (int j = 0; j < 4; ++j) {
        int t = cta * 4 + j;
        for (int i = tid; i < Bsz * Dsz; i += TPB) {
            int b = i >> 7, d = i & 127;
            g_xT[((size_t)t * Bsz + b) * Dsz + d] = X[((size_t)b * Tsz + t) * Dsz + d];
        }
    }
    // ---- prologue: stage this CTA's weight slices (gate-row-major, k contiguous) ----
    for (int g = 0; g < 24; ++g) {
        int u = g / 3, gate = g % 3;
        const float* srcH = Whh + (size_t)(gate * Hsz + U0 + u) * Hsz;
        const float* srcX = Wih + (size_t)(gate * Hsz + U0 + u) * Kx;
        for (int k = tid; k < Hsz; k += TPB) WHs[g * Hsz + k] = srcH[k];
        for (int k = tid; k < Kx;  k += TPB) WXs[g * Hsz + k] = srcX[k];
    }
    // ---- per-thread biases for its unit ----
    const int uu = U0 + unit;
    const float bsr = bih[uu]           + bhh[uu];
    const float bsz = bih[Hsz + uu]     + bhh[Hsz + uu];
    const float bxn = bih[2 * Hsz + uu];
    const float bhn = bhh[2 * Hsz + uu];

    float hp = 0.0f;                            // this thread's own h (carried in register)

    gridbar(1u, cta, tid);                      // xT + h-zero globally visible

    const float* wH0 = WHs + (unit * 3 + 0) * Hsz;
    const float* wH1 = WHs + (unit * 3 + 1) * Hsz;
    const float* wH2 = WHs + (unit * 3 + 2) * Hsz;
    const float* wX0 = WXs + (unit * 3 + 0) * Hsz;
    const float* wX1 = WXs + (unit * 3 + 1) * Hsz;
    const float* wX2 = WXs + (unit * 3 + 2) * Hsz;

    // ---- main pipelined recurrence: iter it computes L0 t=it and L1 t=it-1 ----
    for (int it = 0; it <= Tsz; ++it) {
        bool active = role0 ? (it < Tsz) : (it >= 1);
        if (active) {
            int pb = (it + 1) & 1, cb = it & 1;
            const float* hprev = hbuf + pb * HB;
            float*       hout  = hbuf + cb * HB;
            const float* xsrc; int xstride;
            if (role0) { xsrc = g_xT + (size_t)it * Bsz * Dsz; xstride = Dsz; }
            else       { xsrc = g_h1 + pb * HB;                xstride = Hsz; }

            ull aH[3] = {0, 0, 0};
            ull aX[3] = {0, 0, 0};

            prefetch_chunk(stage_smem, hprev, Hsz, tid);       // chunk 0 -> buf 0
            for (int c = 0; c < NCH; ++c) {
                cpasync_wait0();
                __syncthreads();
                if (c + 1 < NCH) {
                    const float* nsrc = (c + 1 < 4) ? (hprev + (c + 1) * KC)
                                                    : (xsrc  + (c + 1 - 4) * KC);
                    int rs = (c + 1 < 4) ? Hsz : xstride;
                    prefetch_chunk(stage_smem + ((c + 1) & 1) * STG * 4, nsrc, rs, tid);
                }
                const float* hrow = stage + (c & 1) * STG + col * STRD;
                if (c < 4) accum_chunk(wH0 + c * KC, wH1 + c * KC, wH2 + c * KC, hrow, aH);
                else       accum_chunk(wX0 + (c - 4) * KC, wX1 + (c - 4) * KC,
                                       wX2 + (c - 4) * KC, hrow, aX);
            }

            // gates + state update for this (unit, col)
            float r = sigmoidf_(sum2(aH[0]) + sum2(aX[0]) + bsr);
            float z = sigmoidf_(sum2(aH[1]) + sum2(aX[1]) + bsz);
            float n = tanhf_(sum2(aX[2]) + bxn + r * (sum2(aH[2]) + bhn));
            float hn = fmaf(z, hp - n, n);                      // (1-z)*n + z*h
            __stcg(&hout[(size_t)col * Hsz + uu], hn);
            hp = hn;
        }
        gridbar(2u + (unsigned)it, cta, tid);
    }

    // ---- epilogue: FC on final h2 (t=511 written at it=512 into parity 0) ----
    if (cta == 0 && tid < Bsz) {
        const float* h2f = g_h2 + (size_t)tid * Hsz;            // parity 0, [b][k]
        float acc = b_fc[0];
#pragma unroll 8
        for (int u = 0; u < Hsz; ++u)
            acc = fmaf(W_fc[u], __ldcg(&h2f[u]), acc);
        out[tid] = acc;
    }

    // ---- reset barrier state so every graph replay starts clean ----
    __syncthreads();
    __threadfence();
    if (tid == 0) *((volatile unsigned*)&g_flags[cta]) = 0u;
    if (cta == 0) {
        if (tid < NCTA) {
            volatile unsigned* f = &g_flags[tid];
            while (*f != 0u) __nanosleep(32);
        }
        __syncthreads();
        if (tid == 0) {
            __threadfence();
            *((volatile unsigned*)&g_release) = 0u;
        }
    }
}

extern "C" void kernel_launch(void* const* d_in, const int* in_sizes, int n_in,
                              void* d_out, int out_size) {
    (void)in_sizes; (void)n_in; (void)out_size;
    const float* X     = (const float*)d_in[0];
    const float* W_ih0 = (const float*)d_in[1];
    const float* W_hh0 = (const float*)d_in[2];
    const float* b_ih0 = (const float*)d_in[3];
    const float* b_hh0 = (const float*)d_in[4];
    const float* W_ih1 = (const float*)d_in[5];
    const float* W_hh1 = (const float*)d_in[6];
    const float* b_ih1 = (const float*)d_in[7];
    const float* b_hh1 = (const float*)d_in[8];
    const float* W_fc  = (const float*)d_in[9];
    const float* b_fc  = (const float*)d_in[10];

    cudaFuncSetAttribute(gru_persistent,
                         cudaFuncAttributeMaxDynamicSharedMemorySize, SMEM_BYTES);
    gru_persistent<<<NCTA, TPB, SMEM_BYTES>>>(X, W_ih0, W_hh0, b_ih0, b_hh0,
                                              W_ih1, W_hh1, b_ih1, b_hh1,
                                              W_fc, b_fc, (float*)d_out);
}

// round 15
// speedup vs baseline: 1.0386x; 1.0386x over previous
#include <cuda_runtime.h>
#include <cstdint>

// ---------------- problem dims ----------------
#define Bsz   64
#define Tsz   512
#define Dsz   128
#define Hsz   512
#define HB    (Hsz * Bsz)          // 32768 floats per [B][H] slab
#define NCTA  128
#define TPB   256
#define L0CTAS 64
#define L1CTAS 64
#define KC    128                  // k-chunk staged per inner pass
#define STRD  132                  // stage row stride (pad 4 -> conflict-free LDS.128)
#define STG   (Bsz * STRD)         // floats per stage buffer
#define WSTR  512                  // weight row stride in smem

#define SMEM_FLOATS (2 * 24 * WSTR + 2 * STG)
#define SMEM_BYTES  (SMEM_FLOATS * 4)      // 49152*2 + 67584 = 165888 B

typedef unsigned long long ull;

// ---------------- persistent device state ----------------
__device__ __align__(16) float g_xT[(size_t)Tsz * Bsz * Dsz];   // X as [t][b][d]
__device__ __align__(16) float g_h1[(size_t)(Tsz + 1) * HB];    // all L0 outputs; slot 512 = zeros
__device__ __align__(16) float g_h2[2 * HB];                    // L1 hidden, double buffered [b][k]
__device__ unsigned g_flagsF[NCTA];   __device__ unsigned g_relF;   // full-grid barrier
__device__ unsigned g_flags0[L0CTAS]; __device__ unsigned g_rel0;   // L0 group barrier / h1-ready
__device__ unsigned g_flags1[L1CTAS]; __device__ unsigned g_rel1;   // L1 group barrier

// packed f32x2 FMA: full fp32 rate (plain 3-reg FFMA is half rate on sm_103a)
#define FMA2(acc, w, x) asm("fma.rn.f32x2 %0, %1, %2, %0;" : "+l"(acc) : "l"(w), "l"(x))

__device__ __forceinline__ float sum2(ull v) {
    float lo, hi;
    asm("mov.b64 {%0, %1}, %2;" : "=f"(lo), "=f"(hi) : "l"(v));
    return lo + hi;
}
__device__ __forceinline__ float sigmoidf_(float x) {
    return __fdividef(1.0f, 1.0f + __expf(-x));
}
__device__ __forceinline__ float tanhf_(float x) {
    x = fminf(12.0f, fmaxf(-12.0f, x));
    float e = __expf(2.0f * x);
    return __fdividef(e - 1.0f, e + 1.0f);
}
__device__ __forceinline__ uint32_t smem_to_u32(const void* smem_ptr) {
    uint32_t addr;
    asm("{ .reg .u64 tmp; cvta.to.shared.u64 tmp, %1; cvt.u32.u64 %0, tmp; }"
        : "=r"(addr) : "l"(smem_ptr));
    return addr;
}

// cp.async: 16B global->shared via L2 (L2 is the cross-CTA coherence point)
__device__ __forceinline__ void cpasync16(uint32_t smem_dst, const float* gsrc) {
    asm volatile("cp.async.cg.shared.global [%0], [%1], 16;" :: "r"(smem_dst), "l"(gsrc));
}
__device__ __forceinline__ void cpasync_commit() { asm volatile("cp.async.commit_group;"); }
__device__ __forceinline__ void cpasync_wait0()  { asm volatile("cp.async.wait_group 0;"); }

// ---------------- group barrier: distributed flags + master aggregation ----------------
__device__ __forceinline__ void groupbar(volatile unsigned* flags, volatile unsigned* rel,
                                         int n, int lcta, int tid, unsigned val) {
    __syncthreads();
    if (tid == 0) {
        __threadfence();
        flags[lcta] = val;
    }
    if (lcta == 0) {
        if (tid < n) {
            while (flags[tid] < val) __nanosleep(32);
        }
        __syncthreads();
        if (tid == 0) { __threadfence(); *rel = val; }
    }
    if (tid == 0) {
        while (*rel < val) __nanosleep(32);
        __threadfence();
    }
    __syncthreads();
}

// prefetch one 64 x KC chunk into stage ([b][k], stride STRD): 8 x 16B per thread
__device__ __forceinline__ void prefetch_chunk(uint32_t dst, const float* __restrict__ src,
                                               int rstride, int tid) {
#pragma unroll
    for (int i = 0; i < (Bsz * KC) / (4 * TPB); ++i) {     // 8 iters
        int j = tid + i * TPB;
        int b = j >> 5, kq = j & 31;                       // 32 x 16B = one 128-float row
        cpasync16(dst + b * (STRD * 4) + kq * 16, src + (size_t)b * rstride + kq * 4);
    }
    cpasync_commit();
}

// accumulate one KC chunk: thread owns 6 gate-rows (2 units) x 1 batch col.
// Each acc packs (even-k, odd-k) partial sums; summed at the end.
__device__ __forceinline__ void accum_chunk(const float* __restrict__ wbase,   // 6 rows, stride WSTR
                                            const float* __restrict__ hrow,
                                            ull& aR0, ull& aZ0, ull& aN0,
                                            ull& aR1, ull& aZ1, ull& aN1) {
#pragma unroll 4
    for (int kk = 0; kk < KC; kk += 4) {
        ulonglong2 h4 = *reinterpret_cast<const ulonglong2*>(hrow + kk);          // 4 k
        ulonglong2 w0 = *reinterpret_cast<const ulonglong2*>(wbase + 0 * WSTR + kk);
        ulonglong2 w1 = *reinterpret_cast<const ulonglong2*>(wbase + 1 * WSTR + kk);
        ulonglong2 w2 = *reinterpret_cast<const ulonglong2*>(wbase + 2 * WSTR + kk);
        ulonglong2 w3 = *reinterpret_cast<const ulonglong2*>(wbase + 3 * WSTR + kk);
        ulonglong2 w4 = *reinterpret_cast<const ulonglong2*>(wbase + 4 * WSTR + kk);
        ulonglong2 w5 = *reinterpret_cast<const ulonglong2*>(wbase + 5 * WSTR + kk);
        FMA2(aR0, w0.x, h4.x); FMA2(aR0, w0.y, h4.y);
        FMA2(aZ0, w1.x, h4.x); FMA2(aZ0, w1.y, h4.y);
        FMA2(aN0, w2.x, h4.x); FMA2(aN0, w2.y, h4.y);
        FMA2(aR1, w3.x, h4.x); FMA2(aR1, w3.y, h4.y);
        FMA2(aZ1, w4.x, h4.x); FMA2(aZ1, w4.y, h4.y);
        FMA2(aN1, w5.x, h4.x); FMA2(aN1, w5.y, h4.y);
    }
}

// one GRU timestep for this CTA's 8 units: nx X-chunks, writes 2 h values per thread
__device__ __forceinline__ void do_step(const float* __restrict__ hprev,
                                        const float* __restrict__ xsrc, int xstride, int nx,
                                        float* __restrict__ hout,
                                        const float* __restrict__ WHs,
                                        const float* __restrict__ WXs,
                                        const float* __restrict__ stage, uint32_t stage_smem,
                                        int tid, int col, int row, int u0glob,
                                        const float bsr[2], const float bsz_[2],
                                        const float bxn[2], const float bhn[2],
                                        float hp[2]) {
    const int NCH = 4 + nx;
    ull aR0 = 0, aZ0 = 0, aNH0 = 0, aNX0 = 0;
    ull aR1 = 0, aZ1 = 0, aNH1 = 0, aNX1 = 0;

    const float* wH = WHs + row * 6 * WSTR;
    const float* wX = WXs + row * 6 * WSTR;

    prefetch_chunk(stage_smem, hprev, Hsz, tid);           // chunk 0 -> buf 0
    for (int c = 0; c < NCH; ++c) {
        cpasync_wait0();
        __syncthreads();
        if (c + 1 < NCH) {
            const float* nsrc = (c + 1 < 4) ? (hprev + (c + 1) * KC)
                                            : (xsrc + (c + 1 - 4) * KC);
            int rs = (c + 1 < 4) ? Hsz : xstride;
            prefetch_chunk(stage_smem + ((c + 1) & 1) * STG * 4, nsrc, rs, tid);
        }
        const float* hrow = stage + (c & 1) * STG + col * STRD;
        if (c < 4) accum_chunk(wH + c * KC, hrow, aR0, aZ0, aNH0, aR1, aZ1, aNH1);
        else       accum_chunk(wX + (c - 4) * KC, hrow, aR0, aZ0, aNX0, aR1, aZ1, aNX1);
    }

    float hn0, hn1;
    {
        float r = sigmoidf_(sum2(aR0) + bsr[0]);
        float z = sigmoidf_(sum2(aZ0) + bsz_[0]);
        float n = tanhf_(sum2(aNX0) + bxn[0] + r * (sum2(aNH0) + bhn[0]));
        hn0 = fmaf(z, hp[0] - n, n);
    }
    {
        float r = sigmoidf_(sum2(aR1) + bsr[1]);
        float z = sigmoidf_(sum2(aZ1) + bsz_[1]);
        float n = tanhf_(sum2(aNX1) + bxn[1] + r * (sum2(aNH1) + bhn[1]));
        hn1 = fmaf(z, hp[1] - n, n);
    }
    hp[0] = hn0; hp[1] = hn1;
    float2 v = make_float2(hn0, hn1);
    __stcg(reinterpret_cast<float2*>(&hout[(size_t)col * Hsz + u0glob]), v);
}

__global__ __launch_bounds__(TPB)
void gru_persistent(const float* __restrict__ X,
                    const float* __restrict__ W_ih0, const float* __restrict__ W_hh0,
                    const float* __restrict__ b_ih0, const float* __restrict__ b_hh0,
                    const float* __restrict__ W_ih1, const float* __restrict__ W_hh1,
                    const float* __restrict__ b_ih1, const float* __restrict__ b_hh1,
                    const float* __restrict__ W_fc,  const float* __restrict__ b_fc,
                    float* __restrict__ out) {
    extern __shared__ float smem[];
    float* WHs   = smem;                         // [24 gate-rows][WSTR]
    float* WXs   = smem + 24 * WSTR;             // [24 gate-rows][WSTR]
    float* stage = smem + 2 * 24 * WSTR;         // [2][64][STRD]
    const uint32_t stage_smem = smem_to_u32(stage);

    const int tid = threadIdx.x;
    const int cta = blockIdx.x;
    const int col = tid & 63;                    // batch col this thread owns
    const int row = tid >> 6;                    // 0..3: unit-pair group

    const bool role0 = (cta < L0CTAS);
    const int  lcta  = role0 ? cta : (cta - L0CTAS);
    const int  U0    = lcta * 8;
    const int  Kx    = role0 ? Dsz : Hsz;

    const float* Whh = role0 ? W_hh0 : W_hh1;
    const float* Wih = role0 ? W_ih0 : W_ih1;
    const float* bih = role0 ? b_ih0 : b_ih1;
    const float* bhh = role0 ? b_hh0 : b_hh1;

    // ---- prologue: zero h1 "t=-1" slot and both h2 parities ----
    {
        int gid = cta * TPB + tid;
        for (int i = gid; i < HB; i += NCTA * TPB)
            __stcg(&g_h1[(size_t)Tsz * HB + i], 0.0f);
        for (int i = gid; i < 2 * HB; i += NCTA * TPB)
            __stcg(&g_h2[i], 0.0f);
    }
    // ---- prologue: transpose X[b][t][d] -> g_xT[t][b][d] ; 4 timesteps per CTA ----
    for (int j = 0; j < 4; ++j) {
        int t = cta * 4 + j;
        for (int i = tid; i < Bsz * Dsz; i += TPB) {
            int b = i >> 7, d = i & 127;
            __stcg(&g_xT[((size_t)t * Bsz + b) * Dsz + d], X[((size_t)b * Tsz + t) * Dsz + d]);
        }
    }
    // ---- prologue: stage weights (gate-row-major, k contiguous) ----
    // gr = row*6 + lu*3 + gate ; unit = row*2 + lu
    for (int gr = 0; gr < 24; ++gr) {
        int r = gr / 6, rem = gr % 6, lu = rem / 3, gate = rem % 3;
        int u = r * 2 + lu;
        const float* srcH = Whh + (size_t)(gate * Hsz + U0 + u) * Hsz;
        const float* srcX = Wih + (size_t)(gate * Hsz + U0 + u) * Kx;
        for (int k = tid; k < Hsz; k += TPB) WHs[gr * WSTR + k] = srcH[k];
        for (int k = tid; k < Kx;  k += TPB) WXs[gr * WSTR + k] = srcX[k];
    }
    // ---- per-thread biases for its 2 units ----
    const int u0glob = U0 + row * 2;
    float bsr[2], bsz_[2], bxn[2], bhn[2], hp[2] = {0.0f, 0.0f};
#pragma unroll
    for (int u = 0; u < 2; ++u) {
        int uu = u0glob + u;
        bsr[u]  = bih[uu]           + bhh[uu];
        bsz_[u] = bih[Hsz + uu]     + bhh[Hsz + uu];
        bxn[u]  = bih[2 * Hsz + uu];
        bhn[u]  = bhh[2 * Hsz + uu];
    }

    // ---- full-grid barrier: prologue visible everywhere ----
    groupbar(g_flagsF, &g_relF, NCTA, cta, tid, 1u);

    if (role0) {
        // ------- layer 0: free-running, publishes h1[t] + rel0 -------
        for (int t = 0; t < Tsz; ++t) {
            const float* hprev = g_h1 + (size_t)((t == 0) ? Tsz : (t - 1)) * HB;
            do_step(hprev, g_xT + (size_t)t * Bsz * Dsz, Dsz, 1,
                    g_h1 + (size_t)t * HB,
                    WHs, WXs, stage, stage_smem, tid, col, row, u0glob,
                    bsr, bsz_, bxn, bhn, hp);
            groupbar(g_flags0, &g_rel0, L0CTAS, lcta, tid, (unsigned)(t + 1));
        }
    } else {
        // ------- layer 1: consumes h1[t] when ready -------
        for (int t = 0; t < Tsz; ++t) {
            if (tid == 0) {
                volatile unsigned* r0 = &g_rel0;
                while (*r0 < (unsigned)(t + 1)) __nanosleep(64);
                __threadfence();
            }
            __syncthreads();
            const float* hprev = g_h2 + (size_t)((t & 1) ^ 1) * HB;
            do_step(hprev, g_h1 + (size_t)t * HB, Hsz, 4,
                    g_h2 + (size_t)(t & 1) * HB,
                    WHs, WXs, stage, stage_smem, tid, col, row, u0glob,
                    bsr, bsz_, bxn, bhn, hp);
            groupbar(g_flags1, &g_rel1, L1CTAS, lcta, tid, (unsigned)(t + 1));
        }
        // ---- FC epilogue on final h2 (t=511 -> parity 1), by first L1 CTA ----
        if (lcta == 0 && tid < Bsz) {
            const float* h2f = g_h2 + HB + (size_t)tid * Hsz;
            float acc = b_fc[0];
#pragma unroll 8
            for (int u = 0; u < Hsz; ++u)
                acc = fmaf(W_fc[u], __ldcg(&h2f[u]), acc);
            out[tid] = acc;
        }
    }

    // ---- final full-grid barrier, then reset all barrier state for next replay ----
    groupbar(g_flagsF, &g_relF, NCTA, cta, tid, 2u);
    __syncthreads();
    if (tid == 0) {
        __threadfence();
        *((volatile unsigned*)&g_flagsF[cta]) = 0u;
        if (role0) *((volatile unsigned*)&g_flags0[lcta]) = 0u;
        else       *((volatile unsigned*)&g_flags1[lcta]) = 0u;
    }
    if (cta == 0) {
        if (tid < NCTA) {
            volatile unsigned* f = &g_flagsF[tid];
            while (*f != 0u) __nanosleep(32);
        }
        if (tid < L0CTAS) {
            volatile unsigned* f0 = &g_flags0[tid];
            while (*f0 != 0u) __nanosleep(32);
            volatile unsigned* f1 = &g_flags1[tid];
            while (*f1 != 0u) __nanosleep(32);
        }
        __syncthreads();
        if (tid == 0) {
            __threadfence();
            *((volatile unsigned*)&g_rel0) = 0u;
            *((volatile unsigned*)&g_rel1) = 0u;
            *((volatile unsigned*)&g_relF) = 0u;
        }
    }
}

extern "C" void kernel_launch(void* const* d_in, const int* in_sizes, int n_in,
                              void* d_out, int out_size) {
    (void)in_sizes; (void)n_in; (void)out_size;
    const float* X     = (const float*)d_in[0];
    const float* W_ih0 = (const float*)d_in[1];
    const float* W_hh0 = (const float*)d_in[2];
    const float* b_ih0 = (const float*)d_in[3];
    const float* b_hh0 = (const float*)d_in[4];
    const float* W_ih1 = (const float*)d_in[5];
    const float* W_hh1 = (const float*)d_in[6];
    const float* b_ih1 = (const float*)d_in[7];
    const float* b_hh1 = (const float*)d_in[8];
    const float* W_fc  = (const float*)d_in[9];
    const float* b_fc  = (const float*)d_in[10];

    cudaFuncSetAttribute(gru_persistent,
                         cudaFuncAttributeMaxDynamicSharedMemorySize, SMEM_BYTES);
    gru_persistent<<<NCTA, TPB, SMEM_BYTES>>>(X, W_ih0, W_hh0, b_ih0, b_hh0,
                                              W_ih1, W_hh1, b_ih1, b_hh1,
                                              W_fc, b_fc, (float*)d_out);
}

// round 16
// speedup vs baseline: 1.7931x; 1.7265x over previous
#include <cuda_runtime.h>
#include <cstdint>

// ---------------- problem dims ----------------
#define Bsz   64
#define Tsz   512
#define Dsz   128
#define Hsz   512
#define HB    (Hsz * Bsz)        // 32768 floats per h buffer
#define NCTA  128
#define TPB   256
#define L0CTAS 64
#define KC    128                // k-chunk staged per inner pass
// WHs: 512*32 floats (64KB) | WXs: 512*32 (64KB) | stage: 2*KC*64 (64KB)
#define SMEM_FLOATS (512*32 + 512*32 + 2*KC*Bsz)
#define SMEM_BYTES  (SMEM_FLOATS * 4)            // 196608 B

typedef unsigned long long ull;

// ---------------- persistent device state ----------------
__device__ __align__(16) float g_xT[(size_t)Tsz * Dsz * Bsz];  // X transposed to [t][d][b]
__device__ __align__(16) float g_h1[2 * HB];            // layer0 hidden, double buffered, [k][b]
__device__ __align__(16) float g_h2[2 * HB];            // layer1 hidden, double buffered, [k][b]
__device__ unsigned g_flags[NCTA];                      // zero-init; reset at kernel end
__device__ unsigned g_release;                          // zero-init; reset at kernel end

// packed f32x2 ops: full fp32 rate (plain 3-reg FFMA is half rate on sm_103a)
#define FMA2(acc, w, x) asm("fma.rn.f32x2 %0, %1, %2, %0;" : "+l"(acc) : "l"(w), "l"(x))
#define ADD2(d, a, b)   asm("add.rn.f32x2 %0, %1, %2;" : "=l"(d) : "l"(a), "l"(b))

__device__ __forceinline__ void unpack2(ull v, float& lo, float& hi) {
    asm("mov.b64 {%0, %1}, %2;" : "=f"(lo), "=f"(hi) : "l"(v));
}
__device__ __forceinline__ ull dup2(float w) {
    ull r; asm("mov.b64 %0, {%1, %1};" : "=l"(r) : "f"(w)); return r;
}
__device__ __forceinline__ ull pack2(float a, float b) {
    ull r; asm("mov.b64 %0, {%1, %2};" : "=l"(r) : "f"(a), "f"(b)); return r;
}
__device__ __forceinline__ float sigmoidf_(float x) {
    return __fdividef(1.0f, 1.0f + __expf(-x));
}
__device__ __forceinline__ float tanhf_(float x) {
    x = fminf(12.0f, fmaxf(-12.0f, x));
    float e = __expf(2.0f * x);
    return __fdividef(e - 1.0f, e + 1.0f);
}
__device__ __forceinline__ uint32_t smem_to_u32(const void* smem_ptr) {
    uint32_t addr;
    asm("{ .reg .u64 tmp; cvta.to.shared.u64 tmp, %1; cvt.u32.u64 %0, tmp; }"
        : "=r"(addr) : "l"(smem_ptr));
    return addr;
}

// cp.async: 16B global->shared via L2 (L2 is the cross-CTA coherence point)
__device__ __forceinline__ void cpasync16(uint32_t smem_dst, const float* gsrc) {
    asm volatile("cp.async.cg.shared.global [%0], [%1], 16;" :: "r"(smem_dst), "l"(gsrc));
}
__device__ __forceinline__ void cpasync_commit() { asm volatile("cp.async.commit_group;"); }
__device__ __forceinline__ void cpasync_wait0()  { asm volatile("cp.async.wait_group 0;"); }

// ---------------- grid barrier: distributed flags + CTA0 aggregation (R12-proven) ----------------
__device__ __forceinline__ void gridbar(unsigned val, int cta, int tid) {
    __syncthreads();
    if (tid == 0) {
        __threadfence();
        *((volatile unsigned*)&g_flags[cta]) = val;
    }
    if (cta == 0) {
        if (tid < NCTA) {
            volatile unsigned* f = &g_flags[tid];
            while (*f < val) __nanosleep(32);
        }
        __syncthreads();
        if (tid == 0) {
            __threadfence();
            *((volatile unsigned*)&g_release) = val;
        }
    }
    if (tid == 0) {
        volatile unsigned* r = &g_release;
        while (*r < val) __nanosleep(32);
        __threadfence();
    }
    __syncthreads();
}

// prefetch one contiguous KC x 64 chunk ([k][b]) into stage: 8 x 16B per thread
__device__ __forceinline__ void prefetch_chunk(uint32_t dst, const float* __restrict__ src,
                                               int tid) {
#pragma unroll
    for (int i = 0; i < (KC * Bsz) / (4 * TPB); ++i)       // 8 iters
        cpasync16(dst + (tid + i * TPB) * 16, src + (tid + i * TPB) * 4);
    cpasync_commit();
}

// accumulate this thread's 64-k half of one chunk.
// Thread owns 2 units (6 gate-rows) x 2 adjacent cols; each acc packs (col0, col1).
__device__ __forceinline__ void accum_half(const float* __restrict__ Wk,   // [k][32] at half base
                                           const float* __restrict__ hst,  // stage at half base
                                           int cp, int rbase,
                                           ull& aRA, ull& aZA, ull& aNA,
                                           ull& aRB, ull& aZB, ull& aNB) {
#pragma unroll 8
    for (int kk = 0; kk < 64; ++kk) {
        float2 h2 = *reinterpret_cast<const float2*>(hst + kk * Bsz + 2 * cp);   // LDS.64
        ull hh = pack2(h2.x, h2.y);
        float4 wA = *reinterpret_cast<const float4*>(Wk + kk * 32 + rbase);      // broadcast
        float2 wB = *reinterpret_cast<const float2*>(Wk + kk * 32 + rbase + 4);  // broadcast
        FMA2(aRA, dup2(wA.x), hh);
        FMA2(aZA, dup2(wA.y), hh);
        FMA2(aNA, dup2(wA.z), hh);
        FMA2(aRB, dup2(wA.w), hh);
        FMA2(aZB, dup2(wB.x), hh);
        FMA2(aNB, dup2(wB.y), hh);
    }
}

__global__ __launch_bounds__(TPB)
void gru_persistent(const float* __restrict__ X,
                    const float* __restrict__ W_ih0, const float* __restrict__ W_hh0,
                    const float* __restrict__ b_ih0, const float* __restrict__ b_hh0,
                    const float* __restrict__ W_ih1, const float* __restrict__ W_hh1,
                    const float* __restrict__ b_ih1, const float* __restrict__ b_hh1,
                    const float* __restrict__ W_fc,  const float* __restrict__ b_fc,
                    float* __restrict__ out) {
    extern __shared__ float smem[];
    float* WHs   = smem;                    // [512 k][32]: 4 rowgroups x (6 gate w + 2 pad)
    float* WXs   = smem + 512 * 32;         // [Kx k][32]
    float* stage = smem + 2 * 512 * 32;     // [2][KC][64]
    const uint32_t stage_smem = smem_to_u32(stage);

    const int tid   = threadIdx.x;
    const int cta   = blockIdx.x;
    const int khalf = tid >> 7;             // 0: k 0-63 of chunk, 1: k 64-127
    const int tl    = tid & 127;
    const int row   = tl >> 5;              // 0..3 unit-pair rowgroup
    const int cp    = tl & 31;              // col pair: cols {2cp, 2cp+1}
    const int rbase = row * 8;

    const bool role0 = (cta < L0CTAS);
    const int  lcta  = role0 ? cta : (cta - L0CTAS);
    const int  U0    = lcta * 8;            // global hidden-unit base for this CTA
    const int  Kx    = role0 ? Dsz : Hsz;
    const int  NCH   = 4 + Kx / KC;         // 4 H chunks + Kx/KC X chunks

    const float* Whh = role0 ? W_hh0 : W_hh1;
    const float* Wih = role0 ? W_ih0 : W_ih1;
    const float* bih = role0 ? b_ih0 : b_ih1;
    const float* bhh = role0 ? b_hh0 : b_hh1;
    float* hbuf = role0 ? g_h1 : g_h2;

    // ---- prologue: zero h buffers ----
    {
        int gid = cta * TPB + tid;
        for (int i = gid; i < 2 * HB; i += NCTA * TPB) {
            __stcg(&g_h1[i], 0.0f);
            __stcg(&g_h2[i], 0.0f);
        }
    }
    // ---- prologue: transpose X[b][t][d] -> g_xT[t][d][b] ; 4 timesteps per CTA ----
    for (int j = 0; j < 4; ++j) {
        int t = cta * 4 + j;
        for (int i = tid; i < Bsz * Dsz; i += TPB) {
            int d = i >> 6, b = i & 63;
            __stcg(&g_xT[((size_t)t * Dsz + d) * Bsz + b], X[((size_t)b * Tsz + t) * Dsz + d]);
        }
    }
    // ---- prologue: stage weights: [k][32], rowgroup r holds (unit 2r: r,z,n | unit 2r+1: r,z,n) ----
    for (int gu = 0; gu < 24; ++gu) {
        int r = gu / 6, lg = gu % 6;
        int unit = 2 * r + lg / 3, g = lg % 3;
        int grow = g * Hsz + U0 + unit;     // gate order r,z,n
        for (int k = tid; k < Hsz; k += TPB) WHs[k * 32 + r * 8 + lg] = Whh[(size_t)grow * Hsz + k];
        for (int k = tid; k < Kx;  k += TPB) WXs[k * 32 + r * 8 + lg] = Wih[(size_t)grow * Kx  + k];
    }
    // ---- per-thread biases (used by lower half) ----
    const int uA = U0 + row * 2, uB = uA + 1;
    const float bsrA = bih[uA] + bhh[uA],                 bsrB = bih[uB] + bhh[uB];
    const float bszA = bih[Hsz + uA] + bhh[Hsz + uA],     bszB = bih[Hsz + uB] + bhh[Hsz + uB];
    const float bxnA = bih[2 * Hsz + uA],                 bxnB = bih[2 * Hsz + uB];
    const float bhnA = bhh[2 * Hsz + uA],                 bhnB = bhh[2 * Hsz + uB];

    float hpA0 = 0.0f, hpA1 = 0.0f, hpB0 = 0.0f, hpB1 = 0.0f;   // carried h (lower half)

    gridbar(1u, cta, tid);                  // prologue globally visible

    // ---- main pipelined recurrence: iter it computes L0 t=it and L1 t=it-1 ----
    for (int it = 0; it <= Tsz; ++it) {
        bool active = role0 ? (it < Tsz) : (it >= 1);
        if (active) {
            int pb = (it + 1) & 1, cb = it & 1;
            const float* hprev = hbuf + pb * HB;
            float*       hout  = hbuf + cb * HB;
            const float* xsrc  = role0 ? (g_xT + (size_t)it * Dsz * Bsz)
                                       : (g_h1 + pb * HB);

            ull aRA = 0, aZA = 0, aNHA = 0, aNXA = 0;
            ull aRB = 0, aZB = 0, aNHB = 0, aNXB = 0;

            prefetch_chunk(stage_smem, hprev, tid);              // chunk 0 -> buf 0
            for (int c = 0; c < NCH; ++c) {
                cpasync_wait0();
                __syncthreads();
                if (c + 1 < NCH) {
                    const float* nsrc = (c + 1 < 4)
                        ? (hprev + (size_t)(c + 1) * KC * Bsz)
                        : (xsrc  + (size_t)(c + 1 - 4) * KC * Bsz);
                    prefetch_chunk(stage_smem + ((c + 1) & 1) * KC * Bsz * 4, nsrc, tid);
                }
                const float* hst = stage + (c & 1) * KC * Bsz + khalf * 64 * Bsz;
                if (c < 4) {
                    const float* Wk = WHs + (size_t)(c * KC + khalf * 64) * 32;
                    accum_half(Wk, hst, cp, rbase, aRA, aZA, aNHA, aRB, aZB, aNHB);
                } else {
                    const float* Wk = WXs + (size_t)((c - 4) * KC + khalf * 64) * 32;
                    accum_half(Wk, hst, cp, rbase, aRA, aZA, aNXA, aRB, aZB, aNXB);
                }
            }

            // ---- k-split reduction: upper half publishes, lower half combines ----
            __syncthreads();
            ull* red = reinterpret_cast<ull*>(stage);            // 128 x 8 ull = 8KB
            if (khalf) {
                ull* r = red + tl * 8;
                r[0] = aRA; r[1] = aZA; r[2] = aNHA; r[3] = aNXA;
                r[4] = aRB; r[5] = aZB; r[6] = aNHB; r[7] = aNXB;
            }
            __syncthreads();
            if (!khalf) {
                const ull* r = red + tl * 8;
                ADD2(aRA,  aRA,  r[0]); ADD2(aZA,  aZA,  r[1]);
                ADD2(aNHA, aNHA, r[2]); ADD2(aNXA, aNXA, r[3]);
                ADD2(aRB,  aRB,  r[4]); ADD2(aZB,  aZB,  r[5]);
                ADD2(aNHB, aNHB, r[6]); ADD2(aNXB, aNXB, r[7]);

                float sRA0, sRA1, sZA0, sZA1, sNHA0, sNHA1, sNXA0, sNXA1;
                unpack2(aRA,  sRA0,  sRA1);  unpack2(aZA,  sZA0,  sZA1);
                unpack2(aNHA, sNHA0, sNHA1); unpack2(aNXA, sNXA0, sNXA1);
                float sRB0, sRB1, sZB0, sZB1, sNHB0, sNHB1, sNXB0, sNXB1;
                unpack2(aRB,  sRB0,  sRB1);  unpack2(aZB,  sZB0,  sZB1);
                unpack2(aNHB, sNHB0, sNHB1); unpack2(aNXB, sNXB0, sNXB1);

                // unit A, cols 0/1
                {
                    float r0 = sigmoidf_(sRA0 + bsrA), r1 = sigmoidf_(sRA1 + bsrA);
                    float z0 = sigmoidf_(sZA0 + bszA), z1 = sigmoidf_(sZA1 + bszA);
                    float n0 = tanhf_(sNXA0 + bxnA + r0 * (sNHA0 + bhnA));
                    float n1 = tanhf_(sNXA1 + bxnA + r1 * (sNHA1 + bhnA));
                    hpA0 = fmaf(z0, hpA0 - n0, n0);
                    hpA1 = fmaf(z1, hpA1 - n1, n1);
                    __stcg(reinterpret_cast<float2*>(&hout[(size_t)uA * Bsz + 2 * cp]),
                           make_float2(hpA0, hpA1));
                }
                // unit B, cols 0/1
                {
                    float r0 = sigmoidf_(sRB0 + bsrB), r1 = sigmoidf_(sRB1 + bsrB);
                    float z0 = sigmoidf_(sZB0 + bszB), z1 = sigmoidf_(sZB1 + bszB);
                    float n0 = tanhf_(sNXB0 + bxnB + r0 * (sNHB0 + bhnB));
                    float n1 = tanhf_(sNXB1 + bxnB + r1 * (sNHB1 + bhnB));
                    hpB0 = fmaf(z0, hpB0 - n0, n0);
                    hpB1 = fmaf(z1, hpB1 - n1, n1);
                    __stcg(reinterpret_cast<float2*>(&hout[(size_t)uB * Bsz + 2 * cp]),
                           make_float2(hpB0, hpB1));
                }
            }
        }
        gridbar(2u + (unsigned)it, cta, tid);
    }

    // ---- epilogue: FC on final h2 (t=511 written at it=512 into parity 0) ----
    if (cta == 0 && tid < Bsz) {
        const float* h2f = g_h2;            // parity 0, [k][b]
        float acc = b_fc[0];
#pragma unroll 8
        for (int u = 0; u < Hsz; ++u)
            acc = fmaf(W_fc[u], __ldcg(&h2f[(size_t)u * Bsz + tid]), acc);
        out[tid] = acc;
    }

    // ---- reset barrier state so every graph replay starts clean ----
    __syncthreads();
    __threadfence();
    if (tid == 0) *((volatile unsigned*)&g_flags[cta]) = 0u;
    if (cta == 0) {
        if (tid < NCTA) {
            volatile unsigned* f = &g_flags[tid];
            while (*f != 0u) __nanosleep(32);
        }
        __syncthreads();
        if (tid == 0) {
            __threadfence();
            *((volatile unsigned*)&g_release) = 0u;
        }
    }
}

extern "C" void kernel_launch(void* const* d_in, const int* in_sizes, int n_in,
                              void* d_out, int out_size) {
    (void)in_sizes; (void)n_in; (void)out_size;
    const float* X     = (const float*)d_in[0];
    const float* W_ih0 = (const float*)d_in[1];
    const float* W_hh0 = (const float*)d_in[2];
    const float* b_ih0 = (const float*)d_in[3];
    const float* b_hh0 = (const float*)d_in[4];
    const float* W_ih1 = (const float*)d_in[5];
    const float* W_hh1 = (const float*)d_in[6];
    const float* b_ih1 = (const float*)d_in[7];
    const float* b_hh1 = (const float*)d_in[8];
    const float* W_fc  = (const float*)d_in[9];
    const float* b_fc  = (const float*)d_in[10];

    cudaFuncSetAttribute(gru_persistent,
                         cudaFuncAttributeMaxDynamicSharedMemorySize, SMEM_BYTES);
    gru_persistent<<<NCTA, TPB, SMEM_BYTES>>>(X, W_ih0, W_hh0, b_ih0, b_hh0,
                                              W_ih1, W_hh1, b_ih1, b_hh1,
                                              W_fc, b_fc, (float*)d_out);
}

// round 17
// speedup vs baseline: 2.0260x; 1.1299x over previous
#include <cuda_runtime.h>
#include <cstdint>

// ---------------- problem dims ----------------
#define Bsz   64
#define Tsz   512
#define Dsz   128
#define Hsz   512
#define HB    (Hsz * Bsz)        // 32768 floats per h buffer
#define NCTA  128
#define TPB   256
#define L0CTAS 64
#define KC    128                // k-chunk staged per inner pass
#define RSTR  18                 // reduction record stride in ull (144B: bank-spread + 16B aligned)
// WHs: 512*32 floats (64KB) | WXs: 512*32 (64KB) | stage: 2*KC*64 (64KB)
#define SMEM_FLOATS (512*32 + 512*32 + 2*KC*Bsz)
#define SMEM_BYTES  (SMEM_FLOATS * 4)            // 196608 B

typedef unsigned long long ull;

// ---------------- persistent device state ----------------
__device__ __align__(16) float g_xT[(size_t)Tsz * Dsz * Bsz];  // X transposed to [t][d][b]
__device__ __align__(16) float g_h1[2 * HB];            // layer0 hidden, double buffered, [k][b]
__device__ __align__(16) float g_h2[2 * HB];            // layer1 hidden, double buffered, [k][b]
__device__ unsigned g_flags[NCTA];                      // zero-init; reset at kernel end
__device__ unsigned g_release;                          // zero-init; reset at kernel end

// packed f32x2 ops: full fp32 rate (plain 3-reg FFMA is half rate on sm_103a)
#define FMA2(acc, w, x) asm("fma.rn.f32x2 %0, %1, %2, %0;" : "+l"(acc) : "l"(w), "l"(x))
#define ADD2(d, a, b)   asm("add.rn.f32x2 %0, %1, %2;" : "=l"(d) : "l"(a), "l"(b))

__device__ __forceinline__ void unpack2(ull v, float& lo, float& hi) {
    asm("mov.b64 {%0, %1}, %2;" : "=f"(lo), "=f"(hi) : "l"(v));
}
__device__ __forceinline__ ull dup2(float w) {
    ull r; asm("mov.b64 %0, {%1, %1};" : "=l"(r) : "f"(w)); return r;
}
__device__ __forceinline__ float sigmoidf_(float x) {
    return __fdividef(1.0f, 1.0f + __expf(-x));
}
__device__ __forceinline__ float tanhf_(float x) {
    x = fminf(12.0f, fmaxf(-12.0f, x));
    float e = __expf(2.0f * x);
    return __fdividef(e - 1.0f, e + 1.0f);
}
__device__ __forceinline__ uint32_t smem_to_u32(const void* smem_ptr) {
    uint32_t addr;
    asm("{ .reg .u64 tmp; cvta.to.shared.u64 tmp, %1; cvt.u32.u64 %0, tmp; }"
        : "=r"(addr) : "l"(smem_ptr));
    return addr;
}

// cp.async: 16B global->shared via L2 (L2 is the cross-CTA coherence point)
__device__ __forceinline__ void cpasync16(uint32_t smem_dst, const float* gsrc) {
    asm volatile("cp.async.cg.shared.global [%0], [%1], 16;" :: "r"(smem_dst), "l"(gsrc));
}
__device__ __forceinline__ void cpasync_commit() { asm volatile("cp.async.commit_group;"); }
__device__ __forceinline__ void cpasync_wait0()  { asm volatile("cp.async.wait_group 0;"); }

// ---------------- grid barrier: distributed flags + CTA0 aggregation (proven) ----------------
__device__ __forceinline__ void gridbar(unsigned val, int cta, int tid) {
    __syncthreads();
    if (tid == 0) {
        __threadfence();
        *((volatile unsigned*)&g_flags[cta]) = val;
    }
    if (cta == 0) {
        if (tid < NCTA) {
            volatile unsigned* f = &g_flags[tid];
            while (*f < val) __nanosleep(32);
        }
        __syncthreads();
        if (tid == 0) {
            __threadfence();
            *((volatile unsigned*)&g_release) = val;
        }
    }
    if (tid == 0) {
        volatile unsigned* r = &g_release;
        while (*r < val) __nanosleep(32);
        __threadfence();
    }
    __syncthreads();
}

// prefetch one contiguous KC x 64 chunk ([k][b]) into stage: 8 x 16B per thread
__device__ __forceinline__ void prefetch_chunk(uint32_t dst, const float* __restrict__ src,
                                               int tid) {
#pragma unroll
    for (int i = 0; i < (KC * Bsz) / (4 * TPB); ++i)       // 8 iters
        cpasync16(dst + (tid + i * TPB) * 16, src + (tid + i * TPB) * 4);
    cpasync_commit();
}

// accumulate this thread's 32-k quarter of one chunk.
// Thread owns 2 units x 4 cols. acc packs (unit0, unit1) per column.
// Weight layout per k-row rowgroup: [r_u0, r_u1, z_u0, z_u1, n_u0, n_u1, pad, pad]
__device__ __forceinline__ void accum_q(const float* __restrict__ Wk,   // at quarter base
                                        const float* __restrict__ hst,  // at quarter base
                                        int cq, int rbase,
                                        ull* __restrict__ aR, ull* __restrict__ aZ,
                                        ull* __restrict__ aN) {
#pragma unroll 8
    for (int kk = 0; kk < 32; ++kk) {
        float4 h4 = *reinterpret_cast<const float4*>(hst + kk * Bsz + 4 * cq);       // LDS.128
        ulonglong2 wrz = *reinterpret_cast<const ulonglong2*>(Wk + kk * 32 + rbase); // broadcast
        ull wn = *reinterpret_cast<const ull*>(Wk + kk * 32 + rbase + 4);            // broadcast
        ull h0 = dup2(h4.x), h1 = dup2(h4.y), h2 = dup2(h4.z), h3 = dup2(h4.w);
        FMA2(aR[0], wrz.x, h0); FMA2(aZ[0], wrz.y, h0); FMA2(aN[0], wn, h0);
        FMA2(aR[1], wrz.x, h1); FMA2(aZ[1], wrz.y, h1); FMA2(aN[1], wn, h1);
        FMA2(aR[2], wrz.x, h2); FMA2(aZ[2], wrz.y, h2); FMA2(aN[2], wn, h2);
        FMA2(aR[3], wrz.x, h3); FMA2(aZ[3], wrz.y, h3); FMA2(aN[3], wn, h3);
    }
}

__global__ __launch_bounds__(TPB)
void gru_persistent(const float* __restrict__ X,
                    const float* __restrict__ W_ih0, const float* __restrict__ W_hh0,
                    const float* __restrict__ b_ih0, const float* __restrict__ b_hh0,
                    const float* __restrict__ W_ih1, const float* __restrict__ W_hh1,
                    const float* __restrict__ b_ih1, const float* __restrict__ b_hh1,
                    const float* __restrict__ W_fc,  const float* __restrict__ b_fc,
                    float* __restrict__ out) {
    extern __shared__ float smem[];
    float* WHs   = smem;                    // [512 k][32]: 4 rowgroups x 8 (6 used)
    float* WXs   = smem + 512 * 32;         // [Kx k][32]
    float* stage = smem + 2 * 512 * 32;     // [2][KC][64]; buf0 doubles as reduction scratch
    const uint32_t stage_smem = smem_to_u32(stage);

    const int tid  = threadIdx.x;
    const int cta  = blockIdx.x;
    const int ks   = tid >> 6;              // 0..3: k-quarter of each chunk
    const int tl   = tid & 63;
    const int row  = tl >> 4;               // 0..3: unit-pair rowgroup
    const int cq   = tl & 15;               // col quad: cols {4cq..4cq+3}
    const int rbase = row * 8;

    const bool role0 = (cta < L0CTAS);
    const int  lcta  = role0 ? cta : (cta - L0CTAS);
    const int  U0    = lcta * 8;            // global hidden-unit base for this CTA
    const int  Kx    = role0 ? Dsz : Hsz;
    const int  NCH   = 4 + Kx / KC;         // 4 H chunks + Kx/KC X chunks

    const float* Whh = role0 ? W_hh0 : W_hh1;
    const float* Wih = role0 ? W_ih0 : W_ih1;
    const float* bih = role0 ? b_ih0 : b_ih1;
    const float* bhh = role0 ? b_hh0 : b_hh1;
    float* hbuf = role0 ? g_h1 : g_h2;

    // ---- prologue: zero h buffers ----
    {
        int gid = cta * TPB + tid;
        for (int i = gid; i < 2 * HB; i += NCTA * TPB) {
            __stcg(&g_h1[i], 0.0f);
            __stcg(&g_h2[i], 0.0f);
        }
    }
    // ---- prologue: transpose X[b][t][d] -> g_xT[t][d][b] ; 4 timesteps per CTA ----
    for (int j = 0; j < 4; ++j) {
        int t = cta * 4 + j;
        for (int i = tid; i < Bsz * Dsz; i += TPB) {
            int d = i >> 6, b = i & 63;
            __stcg(&g_xT[((size_t)t * Dsz + d) * Bsz + b], X[((size_t)b * Tsz + t) * Dsz + d]);
        }
    }
    // ---- prologue: stage weights: [k][32]; rowgroup r: [r_u0,r_u1,z_u0,z_u1,n_u0,n_u1,-,-] ----
    for (int gi = 0; gi < 24; ++gi) {
        int r = gi / 6, i = gi % 6;
        int gate = i >> 1, ulow = i & 1;
        int grow = gate * Hsz + U0 + r * 2 + ulow;     // gate order r,z,n
        for (int k = tid; k < Hsz; k += TPB) WHs[k * 32 + r * 8 + i] = Whh[(size_t)grow * Hsz + k];
        for (int k = tid; k < Kx;  k += TPB) WXs[k * 32 + r * 8 + i] = Wih[(size_t)grow * Kx  + k];
    }
    // ---- per-thread biases for its 2 units (used by ks==0 threads) ----
    const int uA = U0 + row * 2, uB = uA + 1;
    const float bsrA = bih[uA] + bhh[uA],                 bsrB = bih[uB] + bhh[uB];
    const float bszA = bih[Hsz + uA] + bhh[Hsz + uA],     bszB = bih[Hsz + uB] + bhh[Hsz + uB];
    const float bxnA = bih[2 * Hsz + uA],                 bxnB = bih[2 * Hsz + uB];
    const float bhnA = bhh[2 * Hsz + uA],                 bhnB = bhh[2 * Hsz + uB];

    float hpA[4] = {0, 0, 0, 0}, hpB[4] = {0, 0, 0, 0};   // carried h (ks==0 threads)

    gridbar(1u, cta, tid);                  // prologue globally visible

    // ---- main pipelined recurrence: iter it computes L0 t=it and L1 t=it-1 ----
    for (int it = 0; it <= Tsz; ++it) {
        bool active = role0 ? (it < Tsz) : (it >= 1);
        if (active) {
            int pb = (it + 1) & 1, cb = it & 1;
            const float* hprev = hbuf + pb * HB;
            float*       hout  = hbuf + cb * HB;
            const float* xsrc  = role0 ? (g_xT + (size_t)it * Dsz * Bsz)
                                       : (g_h1 + pb * HB);

            // A[0..3]=aR, A[4..7]=aZ, A[8..11]=aNH, A[12..15]=aNX (each packs (u0,u1))
            ull A[16];
#pragma unroll
            for (int j = 0; j < 16; ++j) A[j] = 0;

            prefetch_chunk(stage_smem, hprev, tid);              // chunk 0 -> buf 0
            for (int c = 0; c < NCH; ++c) {
                cpasync_wait0();
                __syncthreads();
                if (c + 1 < NCH) {
                    const float* nsrc = (c + 1 < 4)
                        ? (hprev + (size_t)(c + 1) * KC * Bsz)
                        : (xsrc  + (size_t)(c + 1 - 4) * KC * Bsz);
                    prefetch_chunk(stage_smem + ((c + 1) & 1) * KC * Bsz * 4, nsrc, tid);
                }
                const float* hst = stage + (c & 1) * KC * Bsz + ks * 32 * Bsz;
                if (c < 4) {
                    const float* Wk = WHs + (size_t)(c * KC + ks * 32) * 32;
                    accum_q(Wk, hst, cq, rbase, A, A + 4, A + 8);
                } else {
                    const float* Wk = WXs + (size_t)((c - 4) * KC + ks * 32) * 32;
                    accum_q(Wk, hst, cq, rbase, A, A + 4, A + 12);
                }
            }

            // ---- k-quarter reduction: ks 1..3 publish, ks 0 combines ----
            __syncthreads();
            ull* red = reinterpret_cast<ull*>(stage);            // 192 records x RSTR ull
            if (ks) {
                ull* rp = red + (size_t)((ks - 1) * 64 + tl) * RSTR;
#pragma unroll
                for (int j = 0; j < 8; ++j) {
                    ulonglong2 v; v.x = A[2 * j]; v.y = A[2 * j + 1];
                    *reinterpret_cast<ulonglong2*>(rp + 2 * j) = v;
                }
            }
            __syncthreads();
            if (ks == 0) {
#pragma unroll
                for (int p = 0; p < 3; ++p) {
                    const ull* rp = red + (size_t)(p * 64 + tl) * RSTR;
#pragma unroll
                    for (int j = 0; j < 8; ++j) {
                        ulonglong2 v = *reinterpret_cast<const ulonglong2*>(rp + 2 * j);
                        ADD2(A[2 * j],     A[2 * j],     v.x);
                        ADD2(A[2 * j + 1], A[2 * j + 1], v.y);
                    }
                }
                // gates + state update: 2 units x 4 cols
#pragma unroll
                for (int j = 0; j < 4; ++j) {
                    float rp0, rp1, zp0, zp1, nh0, nh1, nx0, nx1;
                    unpack2(A[j],      rp0, rp1);
                    unpack2(A[4 + j],  zp0, zp1);
                    unpack2(A[8 + j],  nh0, nh1);
                    unpack2(A[12 + j], nx0, nx1);
                    float r0 = sigmoidf_(rp0 + bsrA), r1 = sigmoidf_(rp1 + bsrB);
                    float z0 = sigmoidf_(zp0 + bszA), z1 = sigmoidf_(zp1 + bszB);
                    float n0 = tanhf_(nx0 + bxnA + r0 * (nh0 + bhnA));
                    float n1 = tanhf_(nx1 + bxnB + r1 * (nh1 + bhnB));
                    hpA[j] = fmaf(z0, hpA[j] - n0, n0);
                    hpB[j] = fmaf(z1, hpB[j] - n1, n1);
                }
                __stcg(reinterpret_cast<float4*>(&hout[(size_t)uA * Bsz + 4 * cq]),
                       make_float4(hpA[0], hpA[1], hpA[2], hpA[3]));
                __stcg(reinterpret_cast<float4*>(&hout[(size_t)uB * Bsz + 4 * cq]),
                       make_float4(hpB[0], hpB[1], hpB[2], hpB[3]));
            }
        }
        gridbar(2u + (unsigned)it, cta, tid);
    }

    // ---- epilogue: FC on final h2 (t=511 written at it=512 into parity 0) ----
    if (cta == 0 && tid < Bsz) {
        const float* h2f = g_h2;            // parity 0, [k][b]
        float acc = b_fc[0];
#pragma unroll 8
        for (int u = 0; u < Hsz; ++u)
            acc = fmaf(W_fc[u], __ldcg(&h2f[(size_t)u * Bsz + tid]), acc);
        out[tid] = acc;
    }

    // ---- reset barrier state so every graph replay starts clean ----
    __syncthreads();
    __threadfence();
    if (tid == 0) *((volatile unsigned*)&g_flags[cta]) = 0u;
    if (cta == 0) {
        if (tid < NCTA) {
            volatile unsigned* f = &g_flags[tid];
            while (*f != 0u) __nanosleep(32);
        }
        __syncthreads();
        if (tid == 0) {
            __threadfence();
            *((volatile unsigned*)&g_release) = 0u;
        }
    }
}

extern "C" void kernel_launch(void* const* d_in, const int* in_sizes, int n_in,
                              void* d_out, int out_size) {
    (void)in_sizes; (void)n_in; (void)out_size;
    const float* X     = (const float*)d_in[0];
    const float* W_ih0 = (const float*)d_in[1];
    const float* W_hh0 = (const float*)d_in[2];
    const float* b_ih0 = (const float*)d_in[3];
    const float* b_hh0 = (const float*)d_in[4];
    const float* W_ih1 = (const float*)d_in[5];
    const float* W_hh1 = (const float*)d_in[6];
    const float* b_ih1 = (const float*)d_in[7];
    const float* b_hh1 = (const float*)d_in[8];
    const float* W_fc  = (const float*)d_in[9];
    const float* b_fc  = (const float*)d_in[10];

    cudaFuncSetAttribute(gru_persistent,
                         cudaFuncAttributeMaxDynamicSharedMemorySize, SMEM_BYTES);
    gru_persistent<<<NCTA, TPB, SMEM_BYTES>>>(X, W_ih0, W_hh0, b_ih0, b_hh0,
                                              W_ih1, W_hh1, b_ih1, b_hh1,
                                              W_fc, b_fc, (float*)d_out);
}